// round 9
// baseline (speedup 1.0000x reference)
#include <cuda_runtime.h>
#include <cstdint>

// LIF forward scan, 4 time steps. x/out: [4, N] fp32, N = 8,388,608.
// Forward value of the surrogate spike == hard threshold (mem > 0.5).
// HBM-bound streaming: 134 MiB read + 134 MiB write.
//
// R8: persistent grid AGAIN, but with the register budget enforced.
// R7 failed because the loop pushed regs 30->40 -> 3 CTAs/SM. Here
// __launch_bounds__(512, 4) pins ptxas to <=32 regs (R6 body needs 30),
// and loop state is minimized to a single bumped index; the four
// per-step offsets are compile-time multiples of n4 folded into the
// addressing. Loads/stores stay evict-first (.cs) -- zero reuse.

static constexpr int STEP      = 4;
static constexpr int GRID_CTAS = 148 * 4;   // one full wave at 4 CTAs/SM
static constexpr int THREADS   = 512;

__device__ __forceinline__ void lif_step(float4& mem, const float4 xin, float4& s) {
    mem.x = fmaf(mem.x, 0.25f, xin.x); mem.y = fmaf(mem.y, 0.25f, xin.y);
    mem.z = fmaf(mem.z, 0.25f, xin.z); mem.w = fmaf(mem.w, 0.25f, xin.w);
    s.x = mem.x > 0.5f ? 1.f : 0.f;  s.y = mem.y > 0.5f ? 1.f : 0.f;
    s.z = mem.z > 0.5f ? 1.f : 0.f;  s.w = mem.w > 0.5f ? 1.f : 0.f;
    mem.x = s.x > 0.f ? 0.f : mem.x; mem.y = s.y > 0.f ? 0.f : mem.y;
    mem.z = s.z > 0.f ? 0.f : mem.z; mem.w = s.w > 0.f ? 0.f : mem.w;
}

__global__ __launch_bounds__(THREADS, 4)   // pin regs <= 32 (2048 thr/SM)
void lif_fwd_kernel(const float4* __restrict__ x, float4* __restrict__ out, int n4) {
    const unsigned stride = GRID_CTAS * THREADS;
    const unsigned n4u = (unsigned)n4;

#pragma unroll 1
    for (unsigned i = blockIdx.x * THREADS + threadIdx.x; i < n4u; i += stride) {
        // 4 independent front-batched LDG.128 (one per time step), evict-first.
        // Offsets are i + t*n4: same two base pointers, constant-folded strides.
        float4 x0 = __ldcs(x + i);
        float4 x1 = __ldcs(x + i + n4u);
        float4 x2 = __ldcs(x + i + 2u * n4u);
        float4 x3 = __ldcs(x + i + 3u * n4u);

        float4 mem = make_float4(0.f, 0.f, 0.f, 0.f);
        float4 s;

        lif_step(mem, x0, s);
        __stcs(out + i, s);

        lif_step(mem, x1, s);
        __stcs(out + i + n4u, s);

        lif_step(mem, x2, s);
        __stcs(out + i + 2u * n4u, s);

        lif_step(mem, x3, s);
        __stcs(out + i + 3u * n4u, s);
    }
}

extern "C" void kernel_launch(void* const* d_in, const int* in_sizes, int n_in,
                              void* d_out, int out_size) {
    const float* x = (const float*)d_in[0];
    float* out = (float*)d_out;

    int total = in_sizes[0];          // STEP * N
    int n = total / STEP;             // 8,388,608 elements per step
    int n4 = n / 4;                   // 2,097,152 float4 per step

    lif_fwd_kernel<<<GRID_CTAS, THREADS>>>((const float4*)x, (float4*)out, n4);
}

// round 10
// speedup vs baseline: 1.1222x; 1.1222x over previous
#include <cuda_runtime.h>
#include <cstdint>

// LIF forward scan, 4 time steps. x/out: [4, N] fp32, N = 8,388,608.
// Forward value of the surrogate spike == hard threshold (mem > 0.5).
// HBM-bound streaming: 134 MiB read + 134 MiB write.
//
// R9: flat grid (persistent variants R7/R8 both lost ~8% in-kernel:
// loop-carried iterations de-batch the load stream behind stores and the
// loop branch; flat grid keeps the L1tex queue fed by fresh CTAs with
// front-batched loads). Block size 512 -> 1024 (2048 CTAs, 2 CTAs/SM,
// same 2048 thr/SM occupancy, half the CTA scheduling events).
// Same 30-reg body as R6; loads/stores evict-first (.cs), zero reuse.

static constexpr int STEP    = 4;
static constexpr int THREADS = 1024;

__device__ __forceinline__ void lif_step(float4& mem, const float4 xin, float4& s) {
    mem.x = fmaf(mem.x, 0.25f, xin.x); mem.y = fmaf(mem.y, 0.25f, xin.y);
    mem.z = fmaf(mem.z, 0.25f, xin.z); mem.w = fmaf(mem.w, 0.25f, xin.w);
    s.x = mem.x > 0.5f ? 1.f : 0.f;  s.y = mem.y > 0.5f ? 1.f : 0.f;
    s.z = mem.z > 0.5f ? 1.f : 0.f;  s.w = mem.w > 0.5f ? 1.f : 0.f;
    mem.x = s.x > 0.f ? 0.f : mem.x; mem.y = s.y > 0.f ? 0.f : mem.y;
    mem.z = s.z > 0.f ? 0.f : mem.z; mem.w = s.w > 0.f ? 0.f : mem.w;
}

__global__ __launch_bounds__(THREADS)
void lif_fwd_kernel(const float4* __restrict__ x, float4* __restrict__ out, int n4) {
    int i = blockIdx.x * THREADS + threadIdx.x;
    if (i >= n4) return;

    // 4 independent front-batched LDG.128 (one per time step), evict-first.
    float4 x0 = __ldcs(&x[0 * (size_t)n4 + i]);
    float4 x1 = __ldcs(&x[1 * (size_t)n4 + i]);
    float4 x2 = __ldcs(&x[2 * (size_t)n4 + i]);
    float4 x3 = __ldcs(&x[3 * (size_t)n4 + i]);

    float4 mem = make_float4(0.f, 0.f, 0.f, 0.f);
    float4 s;

    lif_step(mem, x0, s);
    __stcs(&out[0 * (size_t)n4 + i], s);

    lif_step(mem, x1, s);
    __stcs(&out[1 * (size_t)n4 + i], s);

    lif_step(mem, x2, s);
    __stcs(&out[2 * (size_t)n4 + i], s);

    lif_step(mem, x3, s);
    __stcs(&out[3 * (size_t)n4 + i], s);
}

extern "C" void kernel_launch(void* const* d_in, const int* in_sizes, int n_in,
                              void* d_out, int out_size) {
    const float* x = (const float*)d_in[0];
    float* out = (float*)d_out;

    int total = in_sizes[0];          // STEP * N
    int n = total / STEP;             // 8,388,608 elements per step
    int n4 = n / 4;                   // 2,097,152 float4 per step

    int blocks = (n4 + THREADS - 1) / THREADS;  // 2048
    lif_fwd_kernel<<<blocks, THREADS>>>((const float4*)x, (float4*)out, n4);
}